// round 16
// baseline (speedup 1.0000x reference)
#include <cuda_runtime.h>
#include <math.h>
#include <stdint.h>

#define Bsz 2
#define T 2048
#define Cdim 2048
#define H 16
#define D 128
#define BH (Bsz * H)
#define EPSV 1.1920929e-07f

// ---------------- scratch (static device allocations only) ----------------
__device__ __align__(128) float g_qkv[(size_t)Bsz * T * 3 * Cdim];   // 100 MB
__device__ __align__(128) float g_q[(size_t)BH * T * D];             // 32 MB
__device__ __align__(128) float g_k[(size_t)BH * T * D];             // 32 MB
__device__ __align__(128) float g_v[(size_t)BH * T * D];             // 32 MB
__device__ __align__(128) float g_y[(size_t)Bsz * T * Cdim];         // 32 MB
__device__ __align__(128) float g_cos[T * 64];
__device__ __align__(128) float g_sin[T * 64];

// ---------------- helpers ----------------
__device__ __forceinline__ uint32_t f2tf(float f) {
    uint32_t u;
    asm("cvt.rna.tf32.f32 %0, %1;" : "=r"(u) : "f"(f));
    return u;
}

__device__ __forceinline__ void mma_tf32(float* d, const uint32_t* a,
                                         uint32_t b0, uint32_t b1) {
    asm volatile(
        "mma.sync.aligned.m16n8k8.row.col.f32.tf32.tf32.f32 "
        "{%0,%1,%2,%3}, {%4,%5,%6,%7}, {%8,%9}, {%0,%1,%2,%3};\n"
        : "+f"(d[0]), "+f"(d[1]), "+f"(d[2]), "+f"(d[3])
        : "r"(a[0]), "r"(a[1]), "r"(a[2]), "r"(a[3]), "r"(b0), "r"(b1));
}

// ---------------- RoPE tables ----------------
__global__ void rope_tables_kernel() {
    int t = blockIdx.x;
    int j = threadIdx.x;  // 0..63
    double inv = exp(-((double)j / 64.0) * 13.815510557964274);  // ln(1e6)
    double a = (double)t * inv;
    g_cos[t * 64 + j] = (float)cos(a);
    g_sin[t * 64 + j] = (float)sin(a);
}

// ---------------- deep-BK TF32 GEMM: C[M,N] = A[M,K] @ B[K,N] ----------------
// Block tile 128x128, BK=64, 256 threads, single 82KB dynamic-smem buffer,
// staging in registers: 2 barriers + 128 MMAs/warp per 64-k iteration.
// Layouts identical to the measured-good R13/R15 fragment schemes:
//   A slab (1280 u32): row*10 + slot(k), slot(k) = (k&3)*2 + (k>>2)
//   B slab (1344 u32): octet(n>>3)*84 + (n&7)*10 + slot(k)   (octet-major)
#define GEMM_SMEM_U32 (10240 + 10752)
#define GEMM_SMEM_BYTES (GEMM_SMEM_U32 * 4)

__global__ __launch_bounds__(256, 1)
void gemm_deep_kernel(const float* __restrict__ A, const float* __restrict__ B,
                      float* __restrict__ C, int K, int lda, int ldb, int ldc)
{
    extern __shared__ uint32_t smg[];
    uint32_t* As = smg;          // 8 slabs * 1280
    uint32_t* Bs = smg + 10240;  // 8 slabs * 1344

    const int row0 = blockIdx.y * 128;
    const int col0 = blockIdx.x * 128;
    const int tid  = threadIdx.x;
    const int warp = tid >> 5;
    const int lane = tid & 31;
    const int g = lane >> 2;
    const int c = lane & 3;
    const int wm = (warp >> 1) * 32;
    const int wn = (warp & 1) * 64;

    // A: row = tid>>1, k-offset = (tid&1)*8 within each 16-k sub-slab
    const int a_row = tid >> 1;
    const float* Ap = A + (size_t)(row0 + a_row) * lda + ((tid & 1) << 3);
    uint32_t* As_st = As + (tid & 1) * 1280 + a_row * 10;   // + s*2*1280

    // B: k-row = tid>>4 within 16, octet = tid&15 (8 consecutive n)
    const int kr = tid >> 4;
    const int l  = tid & 15;
    const float* Bp = B + (size_t)kr * ldb + col0 + (l << 3);
    const int kk = kr & 7;
    const int b_coff = ((kk & 3) << 1) + (kk >> 2);
    uint32_t* Bs_st = Bs + (kr >> 3) * 1344 + l * 84 + b_coff;  // + s*2*1344

    const int kperm[8] = {0, 2, 4, 6, 1, 3, 5, 7};

    float ar[4][8], br[4][8];
    auto ldg = [&](int k0) {
#pragma unroll
        for (int s = 0; s < 4; s++) {
            float4 v0 = *(const float4*)(Ap + k0 + s * 16);
            float4 v1 = *(const float4*)(Ap + k0 + s * 16 + 4);
            ar[s][0] = v0.x; ar[s][1] = v0.y; ar[s][2] = v0.z; ar[s][3] = v0.w;
            ar[s][4] = v1.x; ar[s][5] = v1.y; ar[s][6] = v1.z; ar[s][7] = v1.w;
            const float* p = Bp + (size_t)(k0 + s * 16) * ldb;
            float4 w0 = *(const float4*)p;
            float4 w1 = *(const float4*)(p + 4);
            br[s][0] = w0.x; br[s][1] = w0.y; br[s][2] = w0.z; br[s][3] = w0.w;
            br[s][4] = w1.x; br[s][5] = w1.y; br[s][6] = w1.z; br[s][7] = w1.w;
        }
    };

    float acc[2][8][4];
#pragma unroll
    for (int i = 0; i < 2; i++)
#pragma unroll
        for (int j = 0; j < 8; j++)
#pragma unroll
            for (int r = 0; r < 4; r++) acc[i][j][r] = 0.f;

    const int nIter = K >> 6;   // 64-k iterations
    ldg(0);
    for (int it = 0; it < nIter; it++) {
        __syncthreads();   // smem free (previous MMA phase done)
#pragma unroll
        for (int s = 0; s < 4; s++) {
            uint32_t* ast = As_st + s * 2 * 1280;
#pragma unroll
            for (int t2 = 0; t2 < 8; t2++) ast[kperm[t2]] = f2tf(ar[s][t2]);
            uint32_t* bst = Bs_st + s * 2 * 1344;
#pragma unroll
            for (int t2 = 0; t2 < 8; t2++) bst[t2 * 10] = f2tf(br[s][t2]);
        }
        __syncthreads();
        if (it + 1 < nIter) ldg((it + 1) << 6);   // prefetch behind MMAs

#pragma unroll
        for (int ks = 0; ks < 8; ks++) {
            const uint32_t* as = As + ks * 1280;
            const uint32_t* bs = Bs + ks * 1344;
            uint32_t a[2][4];
#pragma unroll
            for (int i = 0; i < 2; i++) {
                int r = wm + i * 16 + g;
                uint2 lo = *(const uint2*)&as[r * 10 + c * 2];
                uint2 hi = *(const uint2*)&as[(r + 8) * 10 + c * 2];
                a[i][0] = lo.x; a[i][1] = hi.x; a[i][2] = lo.y; a[i][3] = hi.y;
            }
#pragma unroll
            for (int j = 0; j < 8; j++) {
                uint2 bb = *(const uint2*)&bs[((wn >> 3) + j) * 84 + g * 10 + c * 2];
#pragma unroll
                for (int i = 0; i < 2; i++)
                    mma_tf32(acc[i][j], a[i], bb.x, bb.y);
            }
        }
    }

#pragma unroll
    for (int i = 0; i < 2; i++) {
        int r0 = row0 + wm + i * 16 + g;
#pragma unroll
        for (int j = 0; j < 8; j++) {
            int col = col0 + wn + j * 8 + c * 2;
            *(float2*)&C[(size_t)r0 * ldc + col] = make_float2(acc[i][j][0], acc[i][j][1]);
            *(float2*)&C[(size_t)(r0 + 8) * ldc + col] = make_float2(acc[i][j][2], acc[i][j][3]);
        }
    }
}

// ---------------- fused flash attention (unchanged from measured R15) ----------
#define FA_SMEM_U32 (20480 + 10752 + 20480 + 512)
#define FA_SMEM_BYTES (FA_SMEM_U32 * 4)

__global__ __launch_bounds__(256, 1)
void flash_attn_kernel()
{
    extern __shared__ uint32_t sm[];
    uint32_t* QS  = sm;              // 20480
    uint32_t* KVS = sm + 20480;      // 10752
    uint32_t* Ps  = sm + 31232;      // 20480
    float* sm_m = (float*)(sm + 51712);   // [2][128]
    float* sm_l = sm_m + 256;             // [2][128]

    const int bh = blockIdx.x;
    const int qt = (int)gridDim.y - 1 - (int)blockIdx.y;   // heavy tiles first
    const float* Q  = g_q + (size_t)bh * T * D;
    const float* Km = g_k + (size_t)bh * T * D;
    const float* V  = g_v + (size_t)bh * T * D;

    const int tid  = threadIdx.x;
    const int warp = tid >> 5;
    const int lane = tid & 31;
    const int g = lane >> 2;
    const int c = lane & 3;
    const int wm = (warp >> 1) * 32;
    const int wn = (warp & 1) * 64;
    const int half = warp & 1;

    const int kperm[8] = {0, 2, 4, 6, 1, 3, 5, 7};
    const int slot0 = ((c & 1) << 2) | (c >> 1);   // P-store slot for k=2c

    const int a_row = tid >> 1;
    const int kr = tid >> 4;
    const int nc = (tid & 15) << 3;
    const int kk7 = kr & 7;
    const int v_coff = ((kk7 & 3) << 1) + (kk7 >> 2);
    uint32_t* QS_st = QS  + (tid & 1) * 1280 + a_row * 10;
    uint32_t* KS_st = KVS + (tid & 1) * 1344 + a_row * 10;
    uint32_t* VS_st = KVS + (kr >> 3) * 1344 + (tid & 15) * 84 + v_coff;

    // ---- stage Q once (persistent, all 16 slabs) ----
    {
        const float* Qp = Q + (size_t)(qt * 128 + a_row) * D + ((tid & 1) << 3);
#pragma unroll
        for (int k0 = 0; k0 < 128; k0 += 16) {
            float4 v0 = *(const float4*)(Qp + k0);
            float4 v1 = *(const float4*)(Qp + k0 + 4);
            float av[8] = {v0.x, v0.y, v0.z, v0.w, v1.x, v1.y, v1.z, v1.w};
            uint32_t* st = QS_st + (k0 >> 3) * 1280;
#pragma unroll
            for (int t2 = 0; t2 < 8; t2++) st[kperm[t2]] = f2tf(av[t2]);
        }
    }

    float oacc[2][8][4];
#pragma unroll
    for (int i = 0; i < 2; i++)
#pragma unroll
        for (int j = 0; j < 8; j++)
#pragma unroll
            for (int r = 0; r < 4; r++) oacc[i][j][r] = 0.f;

    float mrow[4], lsum[4];
    int lr[4];
#pragma unroll
    for (int q = 0; q < 4; q++) {
        mrow[q] = -1e30f; lsum[q] = 0.f;
        lr[q] = wm + 16 * (q >> 1) + 8 * (q & 1) + g;
    }
    const float scale = 1.0f / (float)D;

    for (int kt = 0; kt <= qt; kt++) {
        float acc[2][8][4];
#pragma unroll
        for (int i = 0; i < 2; i++)
#pragma unroll
            for (int j = 0; j < 8; j++)
#pragma unroll
                for (int r = 0; r < 4; r++) acc[i][j][r] = 0.f;

        // ---- S = Q @ K^T in two 64-deep halves ----
#pragma unroll
        for (int h2 = 0; h2 < 2; h2++) {
            __syncthreads();
            {
                const float* Kp = Km + (size_t)(kt * 128 + a_row) * D
                                + h2 * 64 + ((tid & 1) << 3);
#pragma unroll
                for (int k0 = 0; k0 < 64; k0 += 16) {
                    float4 v0 = *(const float4*)(Kp + k0);
                    float4 v1 = *(const float4*)(Kp + k0 + 4);
                    float bv[8] = {v0.x, v0.y, v0.z, v0.w, v1.x, v1.y, v1.z, v1.w};
                    uint32_t* st = KS_st + (k0 >> 3) * 1344;
#pragma unroll
                    for (int t2 = 0; t2 < 8; t2++) st[kperm[t2]] = f2tf(bv[t2]);
                }
            }
            __syncthreads();
#pragma unroll
            for (int ks = 0; ks < 8; ks++) {
                const uint32_t* as = QS + (h2 * 8 + ks) * 1280;
                const uint32_t* bs = KVS + ks * 1344;
                uint32_t a[2][4];
#pragma unroll
                for (int i = 0; i < 2; i++) {
                    int r = wm + i * 16 + g;
                    uint2 lo = *(const uint2*)&as[r * 10 + c * 2];
                    uint2 hi = *(const uint2*)&as[(r + 8) * 10 + c * 2];
                    a[i][0] = lo.x; a[i][1] = hi.x; a[i][2] = lo.y; a[i][3] = hi.y;
                }
#pragma unroll
                for (int j = 0; j < 8; j++) {
                    int n = wn + j * 8 + g;
                    uint2 bb = *(const uint2*)&bs[n * 10 + c * 2];
#pragma unroll
                    for (int i = 0; i < 2; i++)
                        mma_tf32(acc[i][j], a[i], bb.x, bb.y);
                }
            }
        }

        // ---- online softmax update ----
        const bool diag = (kt == qt);
#pragma unroll
        for (int q = 0; q < 4; q++) {
            const int i = q >> 1, rb = (q & 1) * 2;
            float rm = -1e30f;
#pragma unroll
            for (int j = 0; j < 8; j++) {
#pragma unroll
                for (int v = 0; v < 2; v++) {
                    float s = acc[i][j][rb + v] * scale;
                    if (diag && (wn + 8 * j + 2 * c + v > lr[q])) s = -1e30f;
                    acc[i][j][rb + v] = s;
                    rm = fmaxf(rm, s);
                }
            }
            rm = fmaxf(rm, __shfl_xor_sync(0xffffffffu, rm, 1));
            rm = fmaxf(rm, __shfl_xor_sync(0xffffffffu, rm, 2));
            if (c == 0) sm_m[half * 128 + lr[q]] = rm;
        }
        __syncthreads();
        float alpha_s[4];
#pragma unroll
        for (int q = 0; q < 4; q++) {
            const int i = q >> 1, rb = (q & 1) * 2;
            float tm = fmaxf(sm_m[lr[q]], sm_m[128 + lr[q]]);
            float nm = fmaxf(mrow[q], tm);
            float alpha = expf(mrow[q] - nm);
            mrow[q] = nm;
            alpha_s[q] = alpha;
            float rs = 0.f;
#pragma unroll
            for (int j = 0; j < 8; j++) {
#pragma unroll
                for (int v = 0; v < 2; v++) {
                    float p = expf(acc[i][j][rb + v] - nm);
                    acc[i][j][rb + v] = p;
                    rs += p;
                }
            }
            rs += __shfl_xor_sync(0xffffffffu, rs, 1);
            rs += __shfl_xor_sync(0xffffffffu, rs, 2);
            if (c == 0) sm_l[half * 128 + lr[q]] = rs;
#pragma unroll
            for (int j = 0; j < 8; j++) {
                oacc[i][j][rb]     *= alpha;
                oacc[i][j][rb + 1] *= alpha;
            }
        }
        __syncthreads();
#pragma unroll
        for (int q = 0; q < 4; q++)
            lsum[q] = lsum[q] * alpha_s[q] + sm_l[lr[q]] + sm_l[128 + lr[q]];

        // ---- store P (all 16 slabs, A-fragment layout) ----
#pragma unroll
        for (int q = 0; q < 4; q++) {
            const int i = q >> 1, rb = (q & 1) * 2;
            uint32_t* prow = Ps + lr[q] * 10;
#pragma unroll
            for (int j = 0; j < 8; j++) {
                uint32_t* pp = prow + ((wn >> 3) + j) * 1280;
                pp[slot0]     = f2tf(acc[i][j][rb]);
                pp[slot0 + 2] = f2tf(acc[i][j][rb + 1]);
            }
        }

        // ---- O += P @ V in two 64-key halves ----
#pragma unroll
        for (int h2 = 0; h2 < 2; h2++) {
            __syncthreads();
            {
                const float* Vb = V + (size_t)(kt * 128 + h2 * 64 + kr) * D + nc;
#pragma unroll
                for (int sl = 0; sl < 4; sl++) {
                    const float* vp = Vb + (size_t)(sl * 16) * D;
                    float4 w0 = *(const float4*)vp;
                    float4 w1 = *(const float4*)(vp + 4);
                    float bv[8] = {w0.x, w0.y, w0.z, w0.w, w1.x, w1.y, w1.z, w1.w};
                    uint32_t* st = VS_st + sl * 2 * 1344;
#pragma unroll
                    for (int t2 = 0; t2 < 8; t2++) st[t2 * 10] = f2tf(bv[t2]);
                }
            }
            __syncthreads();
#pragma unroll
            for (int ks = 0; ks < 8; ks++) {
                const uint32_t* as = Ps + (h2 * 8 + ks) * 1280;
                const uint32_t* bs = KVS + ks * 1344;
                uint32_t a[2][4];
#pragma unroll
                for (int i = 0; i < 2; i++) {
                    int r = wm + i * 16 + g;
                    uint2 lo = *(const uint2*)&as[r * 10 + c * 2];
                    uint2 hi = *(const uint2*)&as[(r + 8) * 10 + c * 2];
                    a[i][0] = lo.x; a[i][1] = hi.x; a[i][2] = lo.y; a[i][3] = hi.y;
                }
#pragma unroll
                for (int j = 0; j < 8; j++) {
                    uint2 bb = *(const uint2*)&bs[((wn >> 3) + j) * 84 + g * 10 + c * 2];
#pragma unroll
                    for (int i = 0; i < 2; i++)
                        mma_tf32(oacc[i][j], a[i], bb.x, bb.y);
                }
            }
        }
    }

    // ---- epilogue: normalize and write to [B,T,C] ----
    const int b = bh >> 4;
    const int h = bh & 15;
    float* Cbase = g_y + (size_t)b * T * Cdim + h * D;
#pragma unroll
    for (int i = 0; i < 2; i++) {
#pragma unroll
        for (int rp = 0; rp < 2; rp++) {
            const int q = i * 2 + rp;
            const int row = qt * 128 + lr[q];
            const float inv = 1.0f / lsum[q];
            const int rb = rp * 2;
#pragma unroll
            for (int j = 0; j < 8; j++) {
                int col = wn + j * 8 + c * 2;
                *(float2*)&Cbase[(size_t)row * Cdim + col] =
                    make_float2(oacc[i][j][rb] * inv, oacc[i][j][rb + 1] * inv);
            }
        }
    }
}

// ---------------- RMSNorm + RoPE + scatter ----------------
__global__ __launch_bounds__(128)
void qkv_post_kernel(const float* __restrict__ qw, const float* __restrict__ kw)
{
    const int bt = blockIdx.x;
    const int h  = blockIdx.y;
    const int d  = threadIdx.x;
    const int t  = bt & (T - 1);
    const int b  = bt >> 11;
    const float* base = g_qkv + (size_t)bt * (3 * Cdim);
    float qv = base[h * D + d];
    float kv = base[Cdim + h * D + d];
    float vv = base[2 * Cdim + h * D + d];

    float q2 = qv * qv, k2 = kv * kv;
#pragma unroll
    for (int off = 16; off; off >>= 1) {
        q2 += __shfl_xor_sync(0xffffffffu, q2, off);
        k2 += __shfl_xor_sync(0xffffffffu, k2, off);
    }
    __shared__ float rq[4], rk[4];
    if ((d & 31) == 0) { rq[d >> 5] = q2; rk[d >> 5] = k2; }
    __syncthreads();
    float qms = (rq[0] + rq[1] + rq[2] + rq[3]) * (1.f / D);
    float kms = (rk[0] + rk[1] + rk[2] + rk[3]) * (1.f / D);
    float qn = qv * rsqrtf(qms + EPSV) * qw[d];
    float kn = kv * rsqrtf(kms + EPSV) * kw[d];

    __shared__ float sq[128], sk[128];
    sq[d] = qn; sk[d] = kn;
    __syncthreads();
    int j = d & 63;
    float cc = g_cos[t * 64 + j];
    float ss = g_sin[t * 64 + j];
    float qo, ko;
    if (d < 64) { qo = qn * cc - sq[d + 64] * ss; ko = kn * cc - sk[d + 64] * ss; }
    else        { qo = qn * cc + sq[d - 64] * ss; ko = kn * cc + sk[d - 64] * ss; }

    const size_t o = (((size_t)(b * H + h)) * T + t) * D + d;
    g_q[o] = qo; g_k[o] = ko; g_v[o] = vv;
}

// ---------------- launcher ----------------
extern "C" void kernel_launch(void* const* d_in, const int* in_sizes, int n_in,
                              void* d_out, int out_size)
{
    const float* x      = (const float*)d_in[0];
    const float* w_qkv  = (const float*)d_in[1];
    const float* w_proj = (const float*)d_in[2];
    const float* qw     = (const float*)d_in[3];
    const float* kw     = (const float*)d_in[4];
    float* out = (float*)d_out;

    float *p_qkv = nullptr, *p_y = nullptr;
    cudaGetSymbolAddress((void**)&p_qkv, g_qkv);
    cudaGetSymbolAddress((void**)&p_y, g_y);

    cudaFuncSetAttribute(flash_attn_kernel,
                         cudaFuncAttributeMaxDynamicSharedMemorySize,
                         FA_SMEM_BYTES);
    cudaFuncSetAttribute(gemm_deep_kernel,
                         cudaFuncAttributeMaxDynamicSharedMemorySize,
                         GEMM_SMEM_BYTES);

    // 1. RoPE tables
    rope_tables_kernel<<<T, 64>>>();
    // 2. qkv = x @ w_qkv   (M=4096, N=6144, K=2048)
    gemm_deep_kernel<<<dim3(3 * Cdim / 128, (Bsz * T) / 128), 256, GEMM_SMEM_BYTES>>>(
        x, w_qkv, p_qkv, Cdim, Cdim, 3 * Cdim, 3 * Cdim);
    // 3. RMSNorm + RoPE + scatter into [BH,T,D]
    qkv_post_kernel<<<dim3(Bsz * T, H), 128>>>(qw, kw);
    // 4-6. fused flash attention -> g_y
    flash_attn_kernel<<<dim3(BH, T / 128), 256, FA_SMEM_BYTES>>>();
    // 7. out = y @ w_proj  (M=4096, N=2048, K=2048)
    gemm_deep_kernel<<<dim3(Cdim / 128, (Bsz * T) / 128), 256, GEMM_SMEM_BYTES>>>(
        p_y, w_proj, out, Cdim, Cdim, Cdim, Cdim);
}